// round 3
// baseline (speedup 1.0000x reference)
#include <cuda_runtime.h>
#include <cuda_bf16.h>
#include <stdint.h>

#define MAX_NODES 50000
#define MAX_EDGES 800000
#define D_IN      128
#define D_E       64
#define NHEADS    4
#define D_OUTF    32
#define HD        128
#define NEG_SLOPE 0.2f
#define EPS_F     1e-16f

#define SCAN_B 256   // block size for scan kernels

// ---------------- scratch ----------------------------------------------------
__device__ float g_HT[(size_t)MAX_NODES * HD];
__device__ float g_alpha[(size_t)MAX_EDGES * NHEADS];
__device__ int   g_deg[MAX_NODES];
__device__ int   g_off[MAX_NODES + 1];
__device__ int   g_cursor[MAX_NODES];
__device__ int   g_csr_src[MAX_EDGES];
__device__ int   g_csr_eid[MAX_EDGES];
__device__ int   g_part[(MAX_NODES + SCAN_B - 1) / SCAN_B + 1];

// ---------------- packed f32x2 helpers ---------------------------------------
__device__ __forceinline__ unsigned long long f2pack(float a, float b) {
    unsigned long long r;
    asm("mov.b64 %0, {%1, %2};" : "=l"(r) : "f"(a), "f"(b));
    return r;
}
__device__ __forceinline__ unsigned long long ffma2(unsigned long long a,
                                                    unsigned long long b,
                                                    unsigned long long c) {
    unsigned long long d;
    asm("fma.rn.f32x2 %0, %1, %2, %3;" : "=l"(d) : "l"(a), "l"(b), "l"(c));
    return d;
}
__device__ __forceinline__ float f2sum(unsigned long long a) {
    float lo, hi;
    asm("mov.b64 {%0, %1}, %2;" : "=f"(lo), "=f"(hi) : "l"(a));
    return lo + hi;
}
__device__ __forceinline__ uint32_t to_tf32(float f) {
    uint32_t r;
    asm("cvt.rna.tf32.f32 %0, %1;" : "=r"(r) : "f"(f));
    return r;
}

// ---------------- zero degree -------------------------------------------------
__global__ void k_zero(int n_nodes) {
    int i = blockIdx.x * blockDim.x + threadIdx.x;
    if (i < n_nodes) g_deg[i] = 0;
}

// ---------------- HT = H @ W^T -------------------------------------------------
__global__ __launch_bounds__(HD) void k_ht(const float* __restrict__ H,
                                           const float* __restrict__ W,
                                           int n_nodes) {
    int d = threadIdx.x;
    unsigned long long wreg[D_IN / 2];
    const unsigned long long* wrow =
        reinterpret_cast<const unsigned long long*>(W + (size_t)d * D_IN);
#pragma unroll
    for (int i = 0; i < D_IN / 2; i++) wreg[i] = wrow[i];

    __shared__ float4 hs[D_IN / 4];
    for (int n = blockIdx.x; n < n_nodes; n += gridDim.x) {
        if (d < D_IN / 4)
            hs[d] = reinterpret_cast<const float4*>(H + (size_t)n * D_IN)[d];
        __syncthreads();
        unsigned long long acc = f2pack(0.f, 0.f);
#pragma unroll
        for (int i = 0; i < D_IN / 4; i++) {
            float4 h4 = hs[i];
            acc = ffma2(f2pack(h4.x, h4.y), wreg[2 * i + 0], acc);
            acc = ffma2(f2pack(h4.z, h4.w), wreg[2 * i + 1], acc);
        }
        g_HT[(size_t)n * HD + d] = f2sum(acc);
        __syncthreads();
    }
}

// ---------------- degree histogram --------------------------------------------
__global__ void k_hist(const int* __restrict__ ei, int n_edges) {
    int i = blockIdx.x * blockDim.x + threadIdx.x;
    if (i < n_edges) atomicAdd(&g_deg[ei[n_edges + i]], 1);
}

// ---------------- parallel scan (3 kernels) ------------------------------------
__global__ __launch_bounds__(SCAN_B) void k_part(int n_nodes) {
    __shared__ int s[SCAN_B / 32];
    int i = blockIdx.x * SCAN_B + threadIdx.x;
    int v = (i < n_nodes) ? g_deg[i] : 0;
#pragma unroll
    for (int o = 16; o > 0; o >>= 1) v += __shfl_xor_sync(0xffffffffu, v, o);
    if ((threadIdx.x & 31) == 0) s[threadIdx.x >> 5] = v;
    __syncthreads();
    if (threadIdx.x == 0) {
        int t = 0;
#pragma unroll
        for (int j = 0; j < SCAN_B / 32; j++) t += s[j];
        g_part[blockIdx.x] = t;
    }
}

__global__ __launch_bounds__(SCAN_B) void k_scanp(int nblocks) {
    __shared__ int s[SCAN_B];
    int tid = threadIdx.x;
    s[tid] = (tid < nblocks) ? g_part[tid] : 0;
    __syncthreads();
    for (int o = 1; o < SCAN_B; o <<= 1) {
        int v = (tid >= o) ? s[tid - o] : 0;
        __syncthreads();
        s[tid] += v;
        __syncthreads();
    }
    if (tid < nblocks) g_part[tid] = s[tid];  // inclusive
}

__global__ __launch_bounds__(SCAN_B) void k_off(int n_nodes) {
    __shared__ int s[SCAN_B];
    int tid = threadIdx.x;
    int i = blockIdx.x * SCAN_B + tid;
    int v = (i < n_nodes) ? g_deg[i] : 0;
    s[tid] = v;
    __syncthreads();
    for (int o = 1; o < SCAN_B; o <<= 1) {
        int x = (tid >= o) ? s[tid - o] : 0;
        __syncthreads();
        s[tid] += x;
        __syncthreads();
    }
    int base = (blockIdx.x > 0) ? g_part[blockIdx.x - 1] : 0;
    int ex = base + s[tid] - v;
    if (i < n_nodes) {
        g_off[i] = ex;
        g_cursor[i] = ex;
        if (i == n_nodes - 1) g_off[n_nodes] = ex + v;
    }
}

// ---------------- fill CSR -----------------------------------------------------
__global__ void k_fill(const int* __restrict__ ei, int n_edges) {
    int i = blockIdx.x * blockDim.x + threadIdx.x;
    if (i < n_edges) {
        int src = ei[i];
        int dst = ei[n_edges + i];
        int pos = atomicAdd(&g_cursor[dst], 1);
        g_csr_src[pos] = src;
        g_csr_eid[pos] = i;
    }
}

// ---------------- edge alpha: tf32 mma GEMM + epilogue --------------------------
// alpha[e,h] = sum_d att[h,d]*LR(HT[src,h,d]+HT[dst,h,d]+(E@We^T)[e,h,d])
#define ETILE  16
#define E_STR  68    // padded stride for E tile (conflict-free A-frag LDS)
#define ET_STR 136   // padded stride for ET tile

__device__ __forceinline__ void mma_tf32(float& c0, float& c1, float& c2, float& c3,
                                         uint32_t a0, uint32_t a1, uint32_t a2, uint32_t a3,
                                         uint32_t b0, uint32_t b1) {
    asm volatile(
        "mma.sync.aligned.m16n8k8.row.col.f32.tf32.tf32.f32 "
        "{%0,%1,%2,%3}, {%4,%5,%6,%7}, {%8,%9}, {%0,%1,%2,%3};"
        : "+f"(c0), "+f"(c1), "+f"(c2), "+f"(c3)
        : "r"(a0), "r"(a1), "r"(a2), "r"(a3), "r"(b0), "r"(b1));
}

__global__ __launch_bounds__(HD) void k_alpha(const float* __restrict__ E,
                                              const float* __restrict__ We,
                                              const int* __restrict__ ei,
                                              const float* __restrict__ att,
                                              int n_edges) {
    int tid = threadIdx.x;
    int w = tid >> 5;          // warp == head
    int lane = tid & 31;
    int g = lane >> 2;         // group id 0..7
    int t4 = lane & 3;         // thread-in-group 0..3

    // B fragments (We^T) in registers: [kt][nt][2], constant for whole kernel.
    // B element (k, n): b0 at k = kt*8+t4, n = w*32+nt*8+g ; b1 at k+4.
    uint32_t bfrag[D_E / 8][4][2];
#pragma unroll
    for (int kt = 0; kt < D_E / 8; kt++)
#pragma unroll
        for (int nt = 0; nt < 4; nt++) {
            int n = w * 32 + nt * 8 + g;
            int k0 = kt * 8 + t4;
            bfrag[kt][nt][0] = to_tf32(We[(size_t)n * D_E + k0]);
            bfrag[kt][nt][1] = to_tf32(We[(size_t)n * D_E + k0 + 4]);
        }
    float attd = att[tid];

    __shared__ uint32_t esE[ETILE * E_STR];   // tf32-converted E tile
    __shared__ float    esT[ETILE * ET_STR];  // ET results
    __shared__ int ssrc[ETILE], sdst[ETILE];

    int ntiles = (n_edges + ETILE - 1) / ETILE;
    for (int tile = blockIdx.x; tile < ntiles; tile += gridDim.x) {
        int e0 = tile * ETILE;
        int cnt = min(ETILE, n_edges - e0);

        // load E tile (coalesced), convert to tf32, zero-pad tail rows
        for (int i = tid; i < ETILE * D_E; i += HD) {
            int r = i >> 6, c = i & (D_E - 1);
            float v = (r < cnt) ? E[(size_t)(e0 + r) * D_E + c] : 0.f;
            esE[r * E_STR + c] = to_tf32(v);
        }
        if (tid < cnt) ssrc[tid] = ei[e0 + tid];
        if (tid >= 32 && tid < 32 + cnt) sdst[tid - 32] = ei[n_edges + e0 + (tid - 32)];
        __syncthreads();

        // GEMM: 16 edges x 32 dims (per warp), K=64
        float acc[4][4];
#pragma unroll
        for (int nt = 0; nt < 4; nt++)
#pragma unroll
            for (int j = 0; j < 4; j++) acc[nt][j] = 0.f;

#pragma unroll
        for (int kt = 0; kt < D_E / 8; kt++) {
            int base = g * E_STR + kt * 8 + t4;
            uint32_t a0 = esE[base];
            uint32_t a1 = esE[base + 8 * E_STR];
            uint32_t a2 = esE[base + 4];
            uint32_t a3 = esE[base + 8 * E_STR + 4];
#pragma unroll
            for (int nt = 0; nt < 4; nt++)
                mma_tf32(acc[nt][0], acc[nt][1], acc[nt][2], acc[nt][3],
                         a0, a1, a2, a3, bfrag[kt][nt][0], bfrag[kt][nt][1]);
        }

        // spill accumulators to smem: c0:(g, col) c1:(g,col+1) c2:(g+8,col) c3:(g+8,col+1)
#pragma unroll
        for (int nt = 0; nt < 4; nt++) {
            int col = w * 32 + nt * 8 + 2 * t4;
            esT[g * ET_STR + col]           = acc[nt][0];
            esT[g * ET_STR + col + 1]       = acc[nt][1];
            esT[(g + 8) * ET_STR + col]     = acc[nt][2];
            esT[(g + 8) * ET_STR + col + 1] = acc[nt][3];
        }
        __syncthreads();

        // epilogue: thread tid owns dim tid
        for (int t = 0; t < cnt; t++) {
            int src = ssrc[t];
            int dst = sdst[t];
            float x = g_HT[(size_t)src * HD + tid] + g_HT[(size_t)dst * HD + tid]
                      + esT[t * ET_STR + tid];
            float y = (x > 0.f) ? x : NEG_SLOPE * x;
            float p = y * attd;
#pragma unroll
            for (int o = 16; o > 0; o >>= 1)
                p += __shfl_xor_sync(0xffffffffu, p, o);
            if (lane == 0) g_alpha[(size_t)(e0 + t) * NHEADS + w] = p;
        }
        __syncthreads();
    }
}

// ---------------- softmax + aggregation ----------------------------------------
#define AGG_CH 32
__global__ __launch_bounds__(HD) void k_agg(float* __restrict__ out, int n_nodes) {
    int n = blockIdx.x;
    int d = threadIdx.x;
    int w = d >> 5;
    int lane = d & 31;
    int start = g_off[n];
    int end = g_off[n + 1];
    int deg = end - start;

    if (deg == 0) {
        out[(size_t)n * HD + d] = 0.f;
        return;
    }

    float m = -3.4e38f;
    for (int i = start + lane; i < end; i += 32)
        m = fmaxf(m, g_alpha[(size_t)g_csr_eid[i] * NHEADS + w]);
#pragma unroll
    for (int o = 16; o > 0; o >>= 1)
        m = fmaxf(m, __shfl_xor_sync(0xffffffffu, m, o));

    float s = 0.f;
    for (int i = start + lane; i < end; i += 32)
        s += __expf(g_alpha[(size_t)g_csr_eid[i] * NHEADS + w] - m);
#pragma unroll
    for (int o = 16; o > 0; o >>= 1)
        s += __shfl_xor_sync(0xffffffffu, s, o);
    float inv = 1.f / (s + EPS_F);

    __shared__ float cw[AGG_CH * NHEADS];
    __shared__ int cs[AGG_CH];
    float acc = 0.f;
    for (int cb = start; cb < end; cb += AGG_CH) {
        int c = min(AGG_CH, end - cb);
        for (int j = lane; j < c; j += 32) {
            int idx = cb + j;
            int eid = g_csr_eid[idx];
            cw[j * NHEADS + w] = __expf(g_alpha[(size_t)eid * NHEADS + w] - m) * inv;
            if (w == 0) cs[j] = g_csr_src[idx];
        }
        __syncthreads();
#pragma unroll 4
        for (int j = 0; j < c; j++)
            acc = fmaf(cw[j * NHEADS + w], g_HT[(size_t)cs[j] * HD + d], acc);
        __syncthreads();
    }
    out[(size_t)n * HD + d] = acc;
}

// ---------------- launcher ------------------------------------------------------
extern "C" void kernel_launch(void* const* d_in, const int* in_sizes, int n_in,
                              void* d_out, int out_size) {
    const float* H = (const float*)d_in[0];
    const int*   ei = (const int*)d_in[1];
    const float* E = (const float*)d_in[2];
    const float* W = (const float*)d_in[3];
    const float* We = (const float*)d_in[4];
    const float* att = (const float*)d_in[5];
    float* out = (float*)d_out;

    int n_nodes = in_sizes[0] / D_IN;
    int n_edges = in_sizes[1] / 2;
    int nsb = (n_nodes + SCAN_B - 1) / SCAN_B;

    k_zero<<<(n_nodes + 255) / 256, 256>>>(n_nodes);
    k_ht<<<1024, HD>>>(H, W, n_nodes);
    k_hist<<<(n_edges + 255) / 256, 256>>>(ei, n_edges);
    k_part<<<nsb, SCAN_B>>>(n_nodes);
    k_scanp<<<1, SCAN_B>>>(nsb);
    k_off<<<nsb, SCAN_B>>>(n_nodes);
    k_fill<<<(n_edges + 255) / 256, 256>>>(ei, n_edges);
    k_alpha<<<2048, HD>>>(E, We, ei, att, n_edges);
    k_agg<<<n_nodes, HD>>>(out, n_nodes);
}

// round 4
// speedup vs baseline: 1.1884x; 1.1884x over previous
#include <cuda_runtime.h>
#include <cuda_bf16.h>
#include <stdint.h>

#define MAX_NODES 50000
#define MAX_EDGES 800000
#define D_IN      128
#define D_E       64
#define NHEADS    4
#define D_OUTF    32
#define HD        128
#define NEG_SLOPE 0.2f
#define EPS_F     1e-16f

#define SCAN_B 256

// ---------------- scratch ----------------------------------------------------
__device__ float g_HT[(size_t)MAX_NODES * HD];
__device__ float g_alpha[(size_t)MAX_EDGES * NHEADS];
__device__ int   g_deg[MAX_NODES];
__device__ int   g_off[MAX_NODES + 1];
__device__ int   g_cursor[MAX_NODES];
__device__ int   g_csr_src[MAX_EDGES];
__device__ int   g_csr_eid[MAX_EDGES];
__device__ int   g_part[(MAX_NODES + SCAN_B - 1) / SCAN_B + 1];

// ---------------- packed f32x2 helpers ---------------------------------------
__device__ __forceinline__ unsigned long long f2pack(float a, float b) {
    unsigned long long r;
    asm("mov.b64 %0, {%1, %2};" : "=l"(r) : "f"(a), "f"(b));
    return r;
}
__device__ __forceinline__ unsigned long long ffma2(unsigned long long a,
                                                    unsigned long long b,
                                                    unsigned long long c) {
    unsigned long long d;
    asm("fma.rn.f32x2 %0, %1, %2, %3;" : "=l"(d) : "l"(a), "l"(b), "l"(c));
    return d;
}
__device__ __forceinline__ float f2sum(unsigned long long a) {
    float lo, hi;
    asm("mov.b64 {%0, %1}, %2;" : "=f"(lo), "=f"(hi) : "l"(a));
    return lo + hi;
}

// ---------------- zero degree -------------------------------------------------
__global__ void k_zero(int n_nodes) {
    int i = blockIdx.x * blockDim.x + threadIdx.x;
    if (i < n_nodes) g_deg[i] = 0;
}

// ---------------- HT = H @ W^T -------------------------------------------------
__global__ __launch_bounds__(HD) void k_ht(const float* __restrict__ H,
                                           const float* __restrict__ W,
                                           int n_nodes) {
    int d = threadIdx.x;
    unsigned long long wreg[D_IN / 2];
    const unsigned long long* wrow =
        reinterpret_cast<const unsigned long long*>(W + (size_t)d * D_IN);
#pragma unroll
    for (int i = 0; i < D_IN / 2; i++) wreg[i] = wrow[i];

    __shared__ float4 hs[D_IN / 4];
    for (int n = blockIdx.x; n < n_nodes; n += gridDim.x) {
        if (d < D_IN / 4)
            hs[d] = reinterpret_cast<const float4*>(H + (size_t)n * D_IN)[d];
        __syncthreads();
        unsigned long long acc0 = f2pack(0.f, 0.f);
        unsigned long long acc1 = f2pack(0.f, 0.f);
#pragma unroll
        for (int i = 0; i < D_IN / 4; i++) {
            float4 h4 = hs[i];
            acc0 = ffma2(f2pack(h4.x, h4.y), wreg[2 * i + 0], acc0);
            acc1 = ffma2(f2pack(h4.z, h4.w), wreg[2 * i + 1], acc1);
        }
        g_HT[(size_t)n * HD + d] = f2sum(acc0) + f2sum(acc1);
        __syncthreads();
    }
}

// ---------------- degree histogram --------------------------------------------
__global__ void k_hist(const int* __restrict__ ei, int n_edges) {
    int i = blockIdx.x * blockDim.x + threadIdx.x;
    if (i < n_edges) atomicAdd(&g_deg[ei[n_edges + i]], 1);
}

// ---------------- parallel scan (3 kernels) ------------------------------------
__global__ __launch_bounds__(SCAN_B) void k_part(int n_nodes) {
    __shared__ int s[SCAN_B / 32];
    int i = blockIdx.x * SCAN_B + threadIdx.x;
    int v = (i < n_nodes) ? g_deg[i] : 0;
#pragma unroll
    for (int o = 16; o > 0; o >>= 1) v += __shfl_xor_sync(0xffffffffu, v, o);
    if ((threadIdx.x & 31) == 0) s[threadIdx.x >> 5] = v;
    __syncthreads();
    if (threadIdx.x == 0) {
        int t = 0;
#pragma unroll
        for (int j = 0; j < SCAN_B / 32; j++) t += s[j];
        g_part[blockIdx.x] = t;
    }
}

__global__ __launch_bounds__(SCAN_B) void k_scanp(int nblocks) {
    __shared__ int s[SCAN_B];
    int tid = threadIdx.x;
    s[tid] = (tid < nblocks) ? g_part[tid] : 0;
    __syncthreads();
    for (int o = 1; o < SCAN_B; o <<= 1) {
        int v = (tid >= o) ? s[tid - o] : 0;
        __syncthreads();
        s[tid] += v;
        __syncthreads();
    }
    if (tid < nblocks) g_part[tid] = s[tid];  // inclusive
}

__global__ __launch_bounds__(SCAN_B) void k_off(int n_nodes) {
    __shared__ int s[SCAN_B];
    int tid = threadIdx.x;
    int i = blockIdx.x * SCAN_B + tid;
    int v = (i < n_nodes) ? g_deg[i] : 0;
    s[tid] = v;
    __syncthreads();
    for (int o = 1; o < SCAN_B; o <<= 1) {
        int x = (tid >= o) ? s[tid - o] : 0;
        __syncthreads();
        s[tid] += x;
        __syncthreads();
    }
    int base = (blockIdx.x > 0) ? g_part[blockIdx.x - 1] : 0;
    int ex = base + s[tid] - v;
    if (i < n_nodes) {
        g_off[i] = ex;
        g_cursor[i] = ex;
        if (i == n_nodes - 1) g_off[n_nodes] = ex + v;
    }
}

// ---------------- fill CSR -----------------------------------------------------
__global__ void k_fill(const int* __restrict__ ei, int n_edges) {
    int i = blockIdx.x * blockDim.x + threadIdx.x;
    if (i < n_edges) {
        int src = ei[i];
        int dst = ei[n_edges + i];
        int pos = atomicAdd(&g_cursor[dst], 1);
        g_csr_src[pos] = src;
        g_csr_eid[pos] = i;
    }
}

// ---------------- edge alpha logits (FFMA2 GEMV + epilogue) ---------------------
// alpha[e,h] = sum_d att[h,d]*LR(HT[src,h,d]+HT[dst,h,d]+(E@We^T)[e,h,d])
#define ETILE 32
__global__ __launch_bounds__(HD) void k_alpha(const float* __restrict__ E,
                                              const float* __restrict__ We,
                                              const int* __restrict__ ei,
                                              const float* __restrict__ att,
                                              int n_edges) {
    int d = threadIdx.x;
    int w = d >> 5;
    int lane = d & 31;

    unsigned long long wreg[D_E / 2];
    const unsigned long long* wrow =
        reinterpret_cast<const unsigned long long*>(We + (size_t)d * D_E);
#pragma unroll
    for (int i = 0; i < D_E / 2; i++) wreg[i] = wrow[i];
    float attd = att[d];

    __shared__ float4 es[ETILE * (D_E / 4)];  // 32 edges x 64 floats = 8KB
    __shared__ int ssrc[ETILE], sdst[ETILE];

    int ntiles = (n_edges + ETILE - 1) / ETILE;
    for (int tile = blockIdx.x; tile < ntiles; tile += gridDim.x) {
        int e0 = tile * ETILE;
        int cnt = min(ETILE, n_edges - e0);
        for (int i = d; i < cnt * (D_E / 4); i += HD)
            es[i] = reinterpret_cast<const float4*>(E + (size_t)e0 * D_E)[i];
        if (d < cnt) ssrc[d] = ei[e0 + d];
        if (d >= 64 && d < 64 + cnt) sdst[d - 64] = ei[n_edges + e0 + (d - 64)];
        __syncthreads();

#pragma unroll 2
        for (int t = 0; t < cnt; t++) {
            int src = ssrc[t];
            int dst = sdst[t];
            float hsum = g_HT[(size_t)src * HD + d] + g_HT[(size_t)dst * HD + d];
            unsigned long long acc0 = f2pack(0.f, 0.f);
            unsigned long long acc1 = f2pack(0.f, 0.f);
#pragma unroll
            for (int i = 0; i < D_E / 4; i++) {
                float4 ev = es[t * (D_E / 4) + i];
                acc0 = ffma2(f2pack(ev.x, ev.y), wreg[2 * i + 0], acc0);
                acc1 = ffma2(f2pack(ev.z, ev.w), wreg[2 * i + 1], acc1);
            }
            float x = hsum + f2sum(acc0) + f2sum(acc1);
            float y = (x > 0.f) ? x : NEG_SLOPE * x;
            float p = y * attd;
#pragma unroll
            for (int o = 16; o > 0; o >>= 1)
                p += __shfl_xor_sync(0xffffffffu, p, o);
            if (lane == 0) g_alpha[(size_t)(e0 + t) * NHEADS + w] = p;
        }
        __syncthreads();
    }
}

// ---------------- softmax + aggregation ----------------------------------------
#define AGG_CH 32
__global__ __launch_bounds__(HD) void k_agg(float* __restrict__ out, int n_nodes) {
    int n = blockIdx.x;
    int d = threadIdx.x;
    int w = d >> 5;
    int lane = d & 31;
    int start = g_off[n];
    int end = g_off[n + 1];
    int deg = end - start;

    if (deg == 0) {
        out[(size_t)n * HD + d] = 0.f;
        return;
    }

    float m = -3.4e38f;
    for (int i = start + lane; i < end; i += 32)
        m = fmaxf(m, g_alpha[(size_t)g_csr_eid[i] * NHEADS + w]);
#pragma unroll
    for (int o = 16; o > 0; o >>= 1)
        m = fmaxf(m, __shfl_xor_sync(0xffffffffu, m, o));

    float s = 0.f;
    for (int i = start + lane; i < end; i += 32)
        s += __expf(g_alpha[(size_t)g_csr_eid[i] * NHEADS + w] - m);
#pragma unroll
    for (int o = 16; o > 0; o >>= 1)
        s += __shfl_xor_sync(0xffffffffu, s, o);
    float inv = 1.f / (s + EPS_F);

    __shared__ float cw[AGG_CH * NHEADS];
    __shared__ int cs[AGG_CH];
    float acc = 0.f;
    for (int cb = start; cb < end; cb += AGG_CH) {
        int c = min(AGG_CH, end - cb);
        for (int j = lane; j < c; j += 32) {
            int idx = cb + j;
            int eid = g_csr_eid[idx];
            cw[j * NHEADS + w] = __expf(g_alpha[(size_t)eid * NHEADS + w] - m) * inv;
            if (w == 0) cs[j] = g_csr_src[idx];
        }
        __syncthreads();
#pragma unroll 4
        for (int j = 0; j < c; j++)
            acc = fmaf(cw[j * NHEADS + w], g_HT[(size_t)cs[j] * HD + d], acc);
        __syncthreads();
    }
    out[(size_t)n * HD + d] = acc;
}

// ---------------- launcher ------------------------------------------------------
// NOTE: k_alpha placed at launch index 3 so the bench profiler (which captures
// that slot) shows the suspected hotspot. It only depends on k_ht, so this
// reordering is semantics-preserving (single stream).
extern "C" void kernel_launch(void* const* d_in, const int* in_sizes, int n_in,
                              void* d_out, int out_size) {
    const float* H = (const float*)d_in[0];
    const int*   ei = (const int*)d_in[1];
    const float* E = (const float*)d_in[2];
    const float* W = (const float*)d_in[3];
    const float* We = (const float*)d_in[4];
    const float* att = (const float*)d_in[5];
    float* out = (float*)d_out;

    int n_nodes = in_sizes[0] / D_IN;
    int n_edges = in_sizes[1] / 2;
    int nsb = (n_nodes + SCAN_B - 1) / SCAN_B;

    k_zero<<<(n_nodes + 255) / 256, 256>>>(n_nodes);
    k_ht<<<1024, HD>>>(H, W, n_nodes);
    k_hist<<<(n_edges + 255) / 256, 256>>>(ei, n_edges);
    k_alpha<<<2048, HD>>>(E, We, ei, att, n_edges);   // launch index 3 (profiled)
    k_part<<<nsb, SCAN_B>>>(n_nodes);
    k_scanp<<<1, SCAN_B>>>(nsb);
    k_off<<<nsb, SCAN_B>>>(n_nodes);
    k_fill<<<(n_edges + 255) / 256, 256>>>(ei, n_edges);
    k_agg<<<n_nodes, HD>>>(out, n_nodes);
}

// round 5
// speedup vs baseline: 1.9468x; 1.6382x over previous
#include <cuda_runtime.h>
#include <cuda_bf16.h>
#include <stdint.h>

#define MAX_NODES 50000
#define MAX_EDGES 800000
#define D_IN      128
#define D_E       64
#define NHEADS    4
#define D_OUTF    32
#define HD        128
#define NEG_SLOPE 0.2f
#define EPS_F     1e-16f

#define SCAN_B 256

// ---------------- scratch ----------------------------------------------------
__device__ float g_HT[(size_t)MAX_NODES * HD];
__device__ float g_alpha[(size_t)MAX_EDGES * NHEADS];
__device__ int   g_deg[MAX_NODES];
__device__ int   g_off[MAX_NODES + 1];
__device__ int   g_cursor[MAX_NODES];
__device__ int   g_csr_src[MAX_EDGES];
__device__ int   g_csr_eid[MAX_EDGES];
__device__ int   g_part[(MAX_NODES + SCAN_B - 1) / SCAN_B + 1];

// ---------------- packed f32x2 helpers ---------------------------------------
__device__ __forceinline__ unsigned long long f2pack(float a, float b) {
    unsigned long long r;
    asm("mov.b64 %0, {%1, %2};" : "=l"(r) : "f"(a), "f"(b));
    return r;
}
__device__ __forceinline__ unsigned long long ffma2(unsigned long long a,
                                                    unsigned long long b,
                                                    unsigned long long c) {
    unsigned long long d;
    asm("fma.rn.f32x2 %0, %1, %2, %3;" : "=l"(d) : "l"(a), "l"(b), "l"(c));
    return d;
}
__device__ __forceinline__ float f2sum(unsigned long long a) {
    float lo, hi;
    asm("mov.b64 {%0, %1}, %2;" : "=f"(lo), "=f"(hi) : "l"(a));
    return lo + hi;
}
__device__ __forceinline__ uint32_t to_tf32(float f) {
    uint32_t r;
    asm("cvt.rna.tf32.f32 %0, %1;" : "=r"(r) : "f"(f));
    return r;
}

// ---------------- zero degree -------------------------------------------------
__global__ void k_zero(int n_nodes) {
    int i = blockIdx.x * blockDim.x + threadIdx.x;
    if (i < n_nodes) g_deg[i] = 0;
}

// ---------------- HT = H @ W^T -------------------------------------------------
__global__ __launch_bounds__(HD) void k_ht(const float* __restrict__ H,
                                           const float* __restrict__ W,
                                           int n_nodes) {
    int d = threadIdx.x;
    unsigned long long wreg[D_IN / 2];
    const unsigned long long* wrow =
        reinterpret_cast<const unsigned long long*>(W + (size_t)d * D_IN);
#pragma unroll
    for (int i = 0; i < D_IN / 2; i++) wreg[i] = wrow[i];

    __shared__ float4 hs[D_IN / 4];
    for (int n = blockIdx.x; n < n_nodes; n += gridDim.x) {
        if (d < D_IN / 4)
            hs[d] = reinterpret_cast<const float4*>(H + (size_t)n * D_IN)[d];
        __syncthreads();
        unsigned long long acc0 = f2pack(0.f, 0.f);
        unsigned long long acc1 = f2pack(0.f, 0.f);
#pragma unroll
        for (int i = 0; i < D_IN / 4; i++) {
            float4 h4 = hs[i];
            acc0 = ffma2(f2pack(h4.x, h4.y), wreg[2 * i + 0], acc0);
            acc1 = ffma2(f2pack(h4.z, h4.w), wreg[2 * i + 1], acc1);
        }
        g_HT[(size_t)n * HD + d] = f2sum(acc0) + f2sum(acc1);
        __syncthreads();
    }
}

// ---------------- degree histogram --------------------------------------------
__global__ void k_hist(const int* __restrict__ ei, int n_edges) {
    int i = blockIdx.x * blockDim.x + threadIdx.x;
    if (i < n_edges) atomicAdd(&g_deg[ei[n_edges + i]], 1);
}

// ---------------- parallel scan (3 kernels) ------------------------------------
__global__ __launch_bounds__(SCAN_B) void k_part(int n_nodes) {
    __shared__ int s[SCAN_B / 32];
    int i = blockIdx.x * SCAN_B + threadIdx.x;
    int v = (i < n_nodes) ? g_deg[i] : 0;
#pragma unroll
    for (int o = 16; o > 0; o >>= 1) v += __shfl_xor_sync(0xffffffffu, v, o);
    if ((threadIdx.x & 31) == 0) s[threadIdx.x >> 5] = v;
    __syncthreads();
    if (threadIdx.x == 0) {
        int t = 0;
#pragma unroll
        for (int j = 0; j < SCAN_B / 32; j++) t += s[j];
        g_part[blockIdx.x] = t;
    }
}

__global__ __launch_bounds__(SCAN_B) void k_scanp(int nblocks) {
    __shared__ int s[SCAN_B];
    int tid = threadIdx.x;
    s[tid] = (tid < nblocks) ? g_part[tid] : 0;
    __syncthreads();
    for (int o = 1; o < SCAN_B; o <<= 1) {
        int v = (tid >= o) ? s[tid - o] : 0;
        __syncthreads();
        s[tid] += v;
        __syncthreads();
    }
    if (tid < nblocks) g_part[tid] = s[tid];  // inclusive
}

__global__ __launch_bounds__(SCAN_B) void k_off(int n_nodes) {
    __shared__ int s[SCAN_B];
    int tid = threadIdx.x;
    int i = blockIdx.x * SCAN_B + tid;
    int v = (i < n_nodes) ? g_deg[i] : 0;
    s[tid] = v;
    __syncthreads();
    for (int o = 1; o < SCAN_B; o <<= 1) {
        int x = (tid >= o) ? s[tid - o] : 0;
        __syncthreads();
        s[tid] += x;
        __syncthreads();
    }
    int base = (blockIdx.x > 0) ? g_part[blockIdx.x - 1] : 0;
    int ex = base + s[tid] - v;
    if (i < n_nodes) {
        g_off[i] = ex;
        g_cursor[i] = ex;
        if (i == n_nodes - 1) g_off[n_nodes] = ex + v;
    }
}

// ---------------- fill CSR -----------------------------------------------------
__global__ void k_fill(const int* __restrict__ ei, int n_edges) {
    int i = blockIdx.x * blockDim.x + threadIdx.x;
    if (i < n_edges) {
        int src = ei[i];
        int dst = ei[n_edges + i];
        int pos = atomicAdd(&g_cursor[dst], 1);
        g_csr_src[pos] = src;
        g_csr_eid[pos] = i;
    }
}

// ---------------- edge alpha: tf32 MMA, register epilogue ----------------------
// alpha[e,h] = sum_d att[h,d]*LR(HT[src,h,d]+HT[dst,h,d]+(E@We^T)[e,h,d])
#define ETILE 16
#define E_STR 68   // word stride of E tile: g*68 % 32 banks conflict-free, 16B-aligned rows

__device__ __forceinline__ void mma_tf32(float& c0, float& c1, float& c2, float& c3,
                                         uint32_t a0, uint32_t a1, uint32_t a2, uint32_t a3,
                                         uint32_t b0, uint32_t b1) {
    asm volatile(
        "mma.sync.aligned.m16n8k8.row.col.f32.tf32.tf32.f32 "
        "{%0,%1,%2,%3}, {%4,%5,%6,%7}, {%8,%9}, {%0,%1,%2,%3};"
        : "+f"(c0), "+f"(c1), "+f"(c2), "+f"(c3)
        : "r"(a0), "r"(a1), "r"(a2), "r"(a3), "r"(b0), "r"(b1));
}

__global__ __launch_bounds__(HD) void k_alpha(const float* __restrict__ E,
                                              const float* __restrict__ We,
                                              const int* __restrict__ ei,
                                              const float* __restrict__ att,
                                              int n_edges) {
    int tid = threadIdx.x;
    int w = tid >> 5;          // warp == head
    int lane = tid & 31;
    int g = lane >> 2;         // 0..7
    int t4 = lane & 3;         // 0..3

    // B fragments (We, col-major n x k): b0 at (k=kt*8+t4, n=w*32+nt*8+g), b1 at k+4
    uint32_t bfrag[D_E / 8][4][2];
#pragma unroll
    for (int kt = 0; kt < D_E / 8; kt++)
#pragma unroll
        for (int nt = 0; nt < 4; nt++) {
            int n = w * 32 + nt * 8 + g;
            int k0 = kt * 8 + t4;
            bfrag[kt][nt][0] = to_tf32(We[(size_t)n * D_E + k0]);
            bfrag[kt][nt][1] = to_tf32(We[(size_t)n * D_E + k0 + 4]);
        }
    // att coefficients for the 8 cols this thread owns (2 per n-tile)
    float2 attf[4];
#pragma unroll
    for (int nt = 0; nt < 4; nt++) {
        int col0 = w * 32 + nt * 8 + 2 * t4;
        attf[nt] = *reinterpret_cast<const float2*>(att + col0);
    }

    __shared__ uint32_t esE[ETILE * E_STR];
    __shared__ int ssrc[ETILE], sdst[ETILE];

    int ntiles = (n_edges + ETILE - 1) / ETILE;
    for (int tile = blockIdx.x; tile < ntiles; tile += gridDim.x) {
        int e0 = tile * ETILE;
        int cnt = min(ETILE, n_edges - e0);

        // load E tile as tf32: 256 float4, 2 per thread
#pragma unroll
        for (int j = 0; j < 2; j++) {
            int idx = tid + HD * j;          // 0..255
            int r = idx >> 4;                // row 0..15
            int c4 = idx & 15;               // float4 index in row
            float4 v = make_float4(0.f, 0.f, 0.f, 0.f);
            if (r < cnt)
                v = reinterpret_cast<const float4*>(E + (size_t)(e0 + r) * D_E)[c4];
            uint4 u;
            u.x = to_tf32(v.x); u.y = to_tf32(v.y);
            u.z = to_tf32(v.z); u.w = to_tf32(v.w);
            *reinterpret_cast<uint4*>(&esE[r * E_STR + c4 * 4]) = u;
        }
        if (tid < ETILE) ssrc[tid] = (tid < cnt) ? ei[e0 + tid] : 0;
        if (tid >= 32 && tid < 32 + ETILE) {
            int r = tid - 32;
            sdst[r] = (r < cnt) ? ei[n_edges + e0 + r] : 0;
        }
        __syncthreads();

        // GEMM: 16 edges x 32 dims (per warp), K=64
        float acc[4][4];
#pragma unroll
        for (int nt = 0; nt < 4; nt++)
#pragma unroll
            for (int j = 0; j < 4; j++) acc[nt][j] = 0.f;

#pragma unroll
        for (int kt = 0; kt < D_E / 8; kt++) {
            int base = g * E_STR + kt * 8 + t4;
            uint32_t a0 = esE[base];
            uint32_t a1 = esE[base + 8 * E_STR];
            uint32_t a2 = esE[base + 4];
            uint32_t a3 = esE[base + 8 * E_STR + 4];
#pragma unroll
            for (int nt = 0; nt < 4; nt++)
                mma_tf32(acc[nt][0], acc[nt][1], acc[nt][2], acc[nt][3],
                         a0, a1, a2, a3, bfrag[kt][nt][0], bfrag[kt][nt][1]);
        }

        // register epilogue: rows (g, g+8), cols (2t4, 2t4+1) per n-tile
        int sA = ssrc[g],     dA = sdst[g];
        int sB = ssrc[g + 8], dB = sdst[g + 8];
        float pA = 0.f, pB = 0.f;
#pragma unroll
        for (int nt = 0; nt < 4; nt++) {
            int col0 = w * 32 + nt * 8 + 2 * t4;
            float2 hsA = *reinterpret_cast<const float2*>(&g_HT[(size_t)sA * HD + col0]);
            float2 hdA = *reinterpret_cast<const float2*>(&g_HT[(size_t)dA * HD + col0]);
            float2 hsB = *reinterpret_cast<const float2*>(&g_HT[(size_t)sB * HD + col0]);
            float2 hdB = *reinterpret_cast<const float2*>(&g_HT[(size_t)dB * HD + col0]);
            float x0 = acc[nt][0] + hsA.x + hdA.x;
            float x1 = acc[nt][1] + hsA.y + hdA.y;
            float x2 = acc[nt][2] + hsB.x + hdB.x;
            float x3 = acc[nt][3] + hsB.y + hdB.y;
            // leakyrelu(x) = 0.8*max(x,0) + 0.2*x
            float y0 = fmaf(0.8f, fmaxf(x0, 0.f), 0.2f * x0);
            float y1 = fmaf(0.8f, fmaxf(x1, 0.f), 0.2f * x1);
            float y2 = fmaf(0.8f, fmaxf(x2, 0.f), 0.2f * x2);
            float y3 = fmaf(0.8f, fmaxf(x3, 0.f), 0.2f * x3);
            pA = fmaf(attf[nt].x, y0, pA);
            pA = fmaf(attf[nt].y, y1, pA);
            pB = fmaf(attf[nt].x, y2, pB);
            pB = fmaf(attf[nt].y, y3, pB);
        }
        // reduce across the 4-lane quad (cols)
        pA += __shfl_xor_sync(0xffffffffu, pA, 1);
        pA += __shfl_xor_sync(0xffffffffu, pA, 2);
        pB += __shfl_xor_sync(0xffffffffu, pB, 1);
        pB += __shfl_xor_sync(0xffffffffu, pB, 2);
        if (t4 == 0) {
            if (g < cnt)     g_alpha[(size_t)(e0 + g) * NHEADS + w] = pA;
            if (g + 8 < cnt) g_alpha[(size_t)(e0 + g + 8) * NHEADS + w] = pB;
        }
        __syncthreads();
    }
}

// ---------------- softmax + aggregation ----------------------------------------
#define AGG_CH 32
__global__ __launch_bounds__(HD) void k_agg(float* __restrict__ out, int n_nodes) {
    int n = blockIdx.x;
    int d = threadIdx.x;
    int w = d >> 5;
    int lane = d & 31;
    int start = g_off[n];
    int end = g_off[n + 1];
    int deg = end - start;

    if (deg == 0) {
        out[(size_t)n * HD + d] = 0.f;
        return;
    }

    float m = -3.4e38f;
    for (int i = start + lane; i < end; i += 32)
        m = fmaxf(m, g_alpha[(size_t)g_csr_eid[i] * NHEADS + w]);
#pragma unroll
    for (int o = 16; o > 0; o >>= 1)
        m = fmaxf(m, __shfl_xor_sync(0xffffffffu, m, o));

    float s = 0.f;
    for (int i = start + lane; i < end; i += 32)
        s += __expf(g_alpha[(size_t)g_csr_eid[i] * NHEADS + w] - m);
#pragma unroll
    for (int o = 16; o > 0; o >>= 1)
        s += __shfl_xor_sync(0xffffffffu, s, o);
    float inv = 1.f / (s + EPS_F);

    __shared__ float cw[AGG_CH * NHEADS];
    __shared__ int cs[AGG_CH];
    float acc = 0.f;
    for (int cb = start; cb < end; cb += AGG_CH) {
        int c = min(AGG_CH, end - cb);
        for (int j = lane; j < c; j += 32) {
            int idx = cb + j;
            int eid = g_csr_eid[idx];
            cw[j * NHEADS + w] = __expf(g_alpha[(size_t)eid * NHEADS + w] - m) * inv;
            if (w == 0) cs[j] = g_csr_src[idx];
        }
        __syncthreads();
#pragma unroll 4
        for (int j = 0; j < c; j++)
            acc = fmaf(cw[j * NHEADS + w], g_HT[(size_t)cs[j] * HD + d], acc);
        __syncthreads();
    }
    out[(size_t)n * HD + d] = acc;
}

// ---------------- launcher ------------------------------------------------------
extern "C" void kernel_launch(void* const* d_in, const int* in_sizes, int n_in,
                              void* d_out, int out_size) {
    const float* H = (const float*)d_in[0];
    const int*   ei = (const int*)d_in[1];
    const float* E = (const float*)d_in[2];
    const float* W = (const float*)d_in[3];
    const float* We = (const float*)d_in[4];
    const float* att = (const float*)d_in[5];
    float* out = (float*)d_out;

    int n_nodes = in_sizes[0] / D_IN;
    int n_edges = in_sizes[1] / 2;
    int nsb = (n_nodes + SCAN_B - 1) / SCAN_B;

    k_zero<<<(n_nodes + 255) / 256, 256>>>(n_nodes);
    k_ht<<<1024, HD>>>(H, W, n_nodes);
    k_hist<<<(n_edges + 255) / 256, 256>>>(ei, n_edges);
    k_alpha<<<2048, HD>>>(E, We, ei, att, n_edges);   // launch index 3 (profiled)
    k_part<<<nsb, SCAN_B>>>(n_nodes);
    k_scanp<<<1, SCAN_B>>>(nsb);
    k_off<<<nsb, SCAN_B>>>(n_nodes);
    k_fill<<<(n_edges + 255) / 256, 256>>>(ei, n_edges);
    k_agg<<<n_nodes, HD>>>(out, n_nodes);
}